// round 1
// baseline (speedup 1.0000x reference)
#include <cuda_runtime.h>

#define NR 32
#define NA 16

static __device__ __forceinline__ unsigned long long pack2(float lo, float hi) {
    unsigned long long r;
    asm("mov.b64 %0, {%1, %2};" : "=l"(r) : "f"(lo), "f"(hi));
    return r;
}
static __device__ __forceinline__ void unpack2(unsigned long long v, float& lo, float& hi) {
    asm("mov.b64 {%0, %1}, %2;" : "=f"(lo), "=f"(hi) : "l"(v));
}
// packed f32x2 fma: d = a*b + c elementwise on (lo,hi) pairs (Blackwell-only)
static __device__ __forceinline__ unsigned long long fma2(
    unsigned long long a, unsigned long long b, unsigned long long c) {
    unsigned long long d;
    asm("fma.rn.f32x2 %0, %1, %2, %3;" : "=l"(d) : "l"(a), "l"(b), "l"(c));
    return d;
}
static __device__ __forceinline__ unsigned long long add2(
    unsigned long long a, unsigned long long b) {
    unsigned long long d;
    asm("add.rn.f32x2 %0, %1, %2;" : "=l"(d) : "l"(a), "l"(b));
    return d;
}
static __device__ __forceinline__ float ex2(float x) {
    float y;
    asm("ex2.approx.f32 %0, %1;" : "=f"(y) : "f"(x));
    return y;
}

__global__ __launch_bounds__(128)
void tsk_kernel(const float* __restrict__ input,
                const float* __restrict__ frbw,
                const float* __restrict__ C,
                float* __restrict__ out, int B)
{
    // Coefficients pre-duplicated as (v, v) float pairs so LDS.64 broadcast
    // feeds fma.rn.f32x2 directly with no packing MOVs in the hot loop.
    __shared__ unsigned long long s_p[NR * NA];   // -0.5/sigma^2 * log2e
    __shared__ unsigned long long s_q[NR * NA];   //  c/sigma^2  * log2e
    __shared__ unsigned long long s_c[NR * NA];   //  C[r][k+1]
    __shared__ unsigned long long s_rc[NR];       //  sum_k -0.5*(c/sigma)^2 * log2e
    __shared__ unsigned long long s_c0[NR];       //  C[r][0]
    __shared__ float s_ct[NR * NA];               //  scratch for const reduction

    const float L2E = 1.4426950408889634f;
    const int tid = threadIdx.x;

    // --- per-block coefficient precompute (tiny vs main loop) ---
    for (int i = tid; i < NR * NA; i += 128) {
        // Faithful to reference indexing: idx = r*A + k; (sigma, center) overlap
        float sig = frbw[i];
        float cen = frbw[i + 1];
        float is2 = 1.0f / (sig * sig);
        float p = -0.5f * is2 * L2E;
        float q = is2 * cen * L2E;
        int r = i >> 4, k = i & 15;
        float cc = C[r * (NA + 1) + k + 1];
        s_p[i] = pack2(p, p);
        s_q[i] = pack2(q, q);
        s_c[i] = pack2(cc, cc);
        s_ct[i] = p * cen * cen;   // -0.5*is2*c^2*log2e
    }
    __syncthreads();
    if (tid < NR) {
        float acc = 0.0f;
        #pragma unroll
        for (int k = 0; k < NA; k++) acc += s_ct[tid * NA + k];
        s_rc[tid] = pack2(acc, acc);
        float c0 = C[tid * (NA + 1)];
        s_c0[tid] = pack2(c0, c0);
    }
    __syncthreads();

    // --- main: each thread handles 2 samples packed into f32x2 lanes ---
    int s0 = blockIdx.x * 256 + tid;
    int s1 = s0 + 128;
    bool v0 = s0 < B, v1 = s1 < B;
    int l0 = v0 ? s0 : 0;
    int l1 = v1 ? s1 : 0;

    const float4* in4 = (const float4*)input;   // row = 4 x float4 (64B aligned)
    unsigned long long X[NA];
    #pragma unroll
    for (int j = 0; j < 4; j++) {
        float4 a = in4[l0 * 4 + j];
        float4 b = in4[l1 * 4 + j];
        X[j * 4 + 0] = pack2(a.x, b.x);
        X[j * 4 + 1] = pack2(a.y, b.y);
        X[j * 4 + 2] = pack2(a.z, b.z);
        X[j * 4 + 3] = pack2(a.w, b.w);
    }

    unsigned long long num = 0ull;   // packed (0.f, 0.f)
    unsigned long long den = 0ull;

    for (int r = 0; r < NR; r++) {   // rolled: keep code resident in L0 I$
        unsigned long long e  = s_rc[r];
        unsigned long long ch = s_c0[r];
        #pragma unroll
        for (int k = 0; k < NA; k++) {
            // e += (p*x + q)*x ; ch += c*x  -- 3 FFMA2 per antecedent
            unsigned long long t = fma2(s_p[r * NA + k], X[k], s_q[r * NA + k]);
            e  = fma2(t, X[k], e);
            ch = fma2(s_c[r * NA + k], X[k], ch);
        }
        float e0, e1;
        unpack2(e, e0, e1);
        unsigned long long u = pack2(ex2(e0), ex2(e1));  // firing strength
        num = fma2(u, ch, num);
        den = add2(den, u);
    }

    float n0, n1, d0, d1;
    unpack2(num, n0, n1);
    unpack2(den, d0, d1);
    if (v0) out[s0] = n0 / d0;
    if (v1) out[s1] = n1 / d1;
}

extern "C" void kernel_launch(void* const* d_in, const int* in_sizes, int n_in,
                              void* d_out, int out_size)
{
    const float* input = (const float*)d_in[0];   // [B, 16] fp32
    const float* frbw  = (const float*)d_in[1];   // [1024]  fp32
    const float* Cm    = (const float*)d_in[2];   // [32,17] fp32
    float* out = (float*)d_out;                   // [B]     fp32

    int B = in_sizes[0] / NA;
    int blocks = (B + 255) / 256;                 // 2 samples/thread, 128 thr
    tsk_kernel<<<blocks, 128>>>(input, frbw, Cm, out, B);
}